// round 16
// baseline (speedup 1.0000x reference)
#include <cuda_runtime.h>
#include <cuda_fp16.h>
#include <math.h>
#include <stdint.h>

#define BB 2
#define SS 8500
#define CC 512
#define HH 8
#define DD 64
#define DFFN 1024
#define MT (BB*SS)   // 17000
#define NPK 384      // packed off(256)+attn(128)

// GEMM tiling: CTA 128x128, 8 warps x (64x32), BK=64, 2 stages, fp16 inputs
#define BK 64
#define PAh 72            // A smem pitch (halves): 144B; ldmatrix banks 4i mod 32 distinct
#define PBh 136           // B smem pitch (halves): 272B
#define ASTG (128*PAh)    // 9216 halves
#define BSTG (BK*PBh)     // 8704 halves
#define STG  (ASTG+BSTG)  // 17920 halves
#define SMEM_BYTES (2*STG*2)   // 71680 B

// ---------------- scratch ------------------------------------------------------
__device__ __half g_srch[MT*CC];
__device__ __half g_qh  [MT*CC];
__device__ __half g_valh[MT*CC];
__device__ float  g_ol  [MT*NPK];
__device__ __half g_smp [MT*CC];
__device__ float  g_tmp [MT*CC];
__device__ float  g_x   [MT*CC];
__device__ __half g_xh  [MT*CC];
__device__ __half g_hid [MT*DFFN];
__device__ __half g_wvh [CC*CC];
__device__ __half g_wph [CC*NPK];
__device__ float  g_bp  [NPK];
__device__ __half g_woh [CC*CC];
__device__ __half g_w1h [CC*DFFN];
__device__ __half g_w2h [DFFN*CC];

__device__ __forceinline__ uint32_t smem_u32(const void* p) {
    return (uint32_t)__cvta_generic_to_shared(p);
}

__device__ __forceinline__ void ldm_x4(uint32_t* r, uint32_t addr) {
    asm volatile("ldmatrix.sync.aligned.m8n8.x4.shared.b16 {%0,%1,%2,%3}, [%4];"
                 : "=r"(r[0]), "=r"(r[1]), "=r"(r[2]), "=r"(r[3]) : "r"(addr));
}
__device__ __forceinline__ void ldm_x4t(uint32_t* r, uint32_t addr) {
    asm volatile("ldmatrix.sync.aligned.m8n8.x4.trans.shared.b16 {%0,%1,%2,%3}, [%4];"
                 : "=r"(r[0]), "=r"(r[1]), "=r"(r[2]), "=r"(r[3]) : "r"(addr));
}
__device__ __forceinline__ void mma_f16(float* d, const uint32_t* a, uint32_t b0, uint32_t b1) {
    asm volatile(
        "mma.sync.aligned.m16n8k16.row.col.f32.f16.f16.f32 "
        "{%0,%1,%2,%3}, {%4,%5,%6,%7}, {%8,%9}, {%0,%1,%2,%3};"
        : "+f"(d[0]), "+f"(d[1]), "+f"(d[2]), "+f"(d[3])
        : "r"(a[0]), "r"(a[1]), "r"(a[2]), "r"(a[3]), "r"(b0), "r"(b1));
}

// ---------------- one-shot prep -------------------------------------------------
#define N4ADD (MT*CC/4)
#define SEG_WV 65536
#define SEG_WO 131072
#define SEG_W1 262144
#define SEG_W2 393216
__global__ void prep_all(const float* __restrict__ src, const float* __restrict__ pos,
                         __half* __restrict__ qh, __half* __restrict__ srch,
                         const float* __restrict__ wv, const float* __restrict__ wo,
                         const float* __restrict__ w1, const float* __restrict__ w2,
                         const float* __restrict__ w_off, const float* __restrict__ w_attn,
                         const float* __restrict__ b_off, const float* __restrict__ b_attn,
                         __half* __restrict__ wvh, __half* __restrict__ woh,
                         __half* __restrict__ w1h, __half* __restrict__ w2h,
                         __half* __restrict__ wph, float* __restrict__ bp) {
    int i = blockIdx.x * blockDim.x + threadIdx.x;
    if (i < N4ADD) {
        float4 x = ((const float4*)src)[i];
        float4 y = ((const float4*)pos)[i];
        __half2* qo = (__half2*)qh + i * 2;
        __half2* so = (__half2*)srch + i * 2;
        qo[0] = __floats2half2_rn(x.x + y.x, x.y + y.y);
        qo[1] = __floats2half2_rn(x.z + y.z, x.w + y.w);
        so[0] = __floats2half2_rn(x.x, x.y);
        so[1] = __floats2half2_rn(x.z, x.w);
        return;
    }
    int c4 = i - N4ADD;
    if (c4 < SEG_W2) {
        const float* in;
        __half* out;
        int j;
        if (c4 < SEG_WV)      { in = wv; out = wvh; j = c4; }
        else if (c4 < SEG_WO) { in = wo; out = woh; j = c4 - SEG_WV; }
        else if (c4 < SEG_W1) { in = w1; out = w1h; j = c4 - SEG_WO; }
        else                  { in = w2; out = w2h; j = c4 - SEG_W1; }
        float4 v = ((const float4*)in)[j];
        __half2* o = (__half2*)out + j * 2;
        o[0] = __floats2half2_rn(v.x, v.y);
        o[1] = __floats2half2_rn(v.z, v.w);
        return;
    }
    int j = c4 - SEG_W2;
    if (j < CC * NPK) {
        int r = j / NPK, c = j % NPK;
        float v = (c < 256) ? w_off[r * 256 + c] : w_attn[r * 128 + (c - 256)];
        wph[j] = __float2half_rn(v);
    }
    if (j < NPK) bp[j] = (j < 256) ? b_off[j] : b_attn[j - 256];
}

// ================= fp16 GEMM body (BK=64, 2-stage) =============================
template<bool RELU, bool HOUT>
__device__ __forceinline__ void hgemm_body(const __half* __restrict__ A,
                                           const __half* __restrict__ Bm,
                                           const float* __restrict__ bias,
                                           void* __restrict__ Cv,
                                           int M, int N, int K, __half* smh)
{
    const int tid  = threadIdx.x;
    const int lane = tid & 31;
    const int wid  = tid >> 5;
    const int wm   = (wid & 1) * 64;
    const int wn   = (wid >> 1) * 32;
    const int mb   = blockIdx.y * 128;
    const int nb   = blockIdx.x * 128;
    const int g    = lane >> 2;
    const int t    = lane & 3;
    const int l15  = lane & 15;
    const int lhi  = lane >> 4;

    float acc[4][4][4];
    #pragma unroll
    for (int i = 0; i < 4; i++)
        #pragma unroll
        for (int j = 0; j < 4; j++)
            #pragma unroll
            for (int r = 0; r < 4; r++) acc[i][j][r] = 0.f;

#define LOADH(buf, kt)                                                             \
    {                                                                              \
        __half* as = smh + (buf) * STG;                                            \
        __half* bs = smh + (buf) * STG + ASTG;                                     \
        _Pragma("unroll")                                                          \
        for (int i = 0; i < 4; i++) {                                              \
            int lin = tid + 256 * i;                                               \
            int row = lin >> 3;                                                    \
            int chk = (lin & 7) * 8;                                               \
            const __half* gp = A + (size_t)(mb + row) * K + (kt) + chk;            \
            uint32_t sa = smem_u32(as + row * PAh + chk);                          \
            int zf = (mb + row < M) ? 16 : 0;                                      \
            asm volatile("cp.async.cg.shared.global [%0], [%1], 16, %2;"           \
                         :: "r"(sa), "l"(gp), "r"(zf));                            \
        }                                                                          \
        _Pragma("unroll")                                                          \
        for (int i = 0; i < 4; i++) {                                              \
            int lin = tid + 256 * i;                                               \
            int k = lin >> 4;                                                      \
            int chk = (lin & 15) * 8;                                              \
            const __half* gp = Bm + (size_t)((kt) + k) * N + nb + chk;             \
            uint32_t sa = smem_u32(bs + k * PBh + chk);                            \
            asm volatile("cp.async.cg.shared.global [%0], [%1], 16;"               \
                         :: "r"(sa), "l"(gp));                                     \
        }                                                                          \
        asm volatile("cp.async.commit_group;");                                    \
    }

    const int NIT = K / BK;
    LOADH(0, 0);

    for (int it = 0; it < NIT; it++) {
        const int buf = it & 1;
        if (it + 1 < NIT) {
            LOADH(1 - buf, (it + 1) * BK);
            asm volatile("cp.async.wait_group 1;");
        } else {
            asm volatile("cp.async.wait_group 0;");
        }
        __syncthreads();

        const __half* ab = smh + buf * STG;
        const __half* bb = smh + buf * STG + ASTG;
        #pragma unroll
        for (int k0 = 0; k0 < BK; k0 += 16) {
            uint32_t af[4][4];
            uint32_t bf[2][4];
            #pragma unroll
            for (int mt = 0; mt < 4; mt++) {
                uint32_t sa = smem_u32((__half*)ab + (wm + mt * 16 + l15) * PAh + k0 + lhi * 8);
                ldm_x4(af[mt], sa);
            }
            #pragma unroll
            for (int nh = 0; nh < 2; nh++) {
                uint32_t sa = smem_u32((__half*)bb + (k0 + l15) * PBh + wn + nh * 16 + lhi * 8);
                ldm_x4t(bf[nh], sa);
            }
            #pragma unroll
            for (int mt = 0; mt < 4; mt++)
                #pragma unroll
                for (int nt = 0; nt < 4; nt++)
                    mma_f16(acc[mt][nt], af[mt], bf[nt >> 1][(nt & 1) * 2], bf[nt >> 1][(nt & 1) * 2 + 1]);
        }
        __syncthreads();
    }
#undef LOADH

    #pragma unroll
    for (int mt = 0; mt < 4; mt++) {
        const int r0 = mb + wm + mt * 16 + g;
        const int r1 = r0 + 8;
        #pragma unroll
        for (int nt = 0; nt < 4; nt++) {
            const int c = nb + wn + nt * 8 + t * 2;
            const float b0 = __ldg(bias + c);
            const float b1 = __ldg(bias + c + 1);
            float v0 = acc[mt][nt][0] + b0;
            float v1 = acc[mt][nt][1] + b1;
            float v2 = acc[mt][nt][2] + b0;
            float v3 = acc[mt][nt][3] + b1;
            if (RELU) {
                v0 = fmaxf(v0, 0.f); v1 = fmaxf(v1, 0.f);
                v2 = fmaxf(v2, 0.f); v3 = fmaxf(v3, 0.f);
            }
            if (HOUT) {
                __half* Ch = (__half*)Cv;
                if (r0 < M) *(__half2*)(Ch + (size_t)r0 * N + c) = __floats2half2_rn(v0, v1);
                if (r1 < M) *(__half2*)(Ch + (size_t)r1 * N + c) = __floats2half2_rn(v2, v3);
            } else {
                float* Cf = (float*)Cv;
                if (r0 < M) *(float2*)(Cf + (size_t)r0 * N + c) = make_float2(v0, v1);
                if (r1 < M) *(float2*)(Cf + (size_t)r1 * N + c) = make_float2(v2, v3);
            }
        }
    }
}

template<bool RELU, bool HOUT>
__global__ __launch_bounds__(256, 2)
void hgemm(const __half* __restrict__ A, const __half* __restrict__ Bm,
           const float* __restrict__ bias, void* __restrict__ Cv,
           int M, int N, int K)
{
    extern __shared__ __align__(16) __half smh[];
    hgemm_body<RELU, HOUT>(A, Bm, bias, Cv, M, N, K, smh);
}

// fused: z=0 value GEMM (N=512, fp16 out), z=1 off|lgt GEMM (N=384, fp32 out)
__global__ __launch_bounds__(256, 2)
void hgemm_dual(const __half* __restrict__ A0, const __half* __restrict__ B0,
                const float* __restrict__ bias0, __half* __restrict__ C0,
                const __half* __restrict__ A1, const __half* __restrict__ B1,
                const float* __restrict__ bias1, float* __restrict__ C1)
{
    extern __shared__ __align__(16) __half smh[];
    if (blockIdx.z == 0) {
        hgemm_body<false, true>(A0, B0, bias0, C0, MT, CC, CC, smh);
    } else {
        if (blockIdx.x >= NPK / 128) return;
        hgemm_body<false, false>(A1, B1, bias1, C1, MT, NPK, CC, smh);
    }
}

// ---------------- deformable sampling: hfma2 bilinear -------------------------
__global__ void sample_kernel(const __half* __restrict__ value,
                              const float* __restrict__ ol,
                              __half* __restrict__ out) {
    int gw = (blockIdx.x * blockDim.x + threadIdx.x) >> 5;
    if (gw >= MT * 4) return;
    const int lane = threadIdx.x & 31;
    const int hp = gw & 3;
    const int bs = gw >> 2;
    const int s  = bs % SS;
    const int rowb = bs - s;
    const int hl = lane >> 4;
    const int li = lane & 15;
    const int head = hp * 2 + hl;

    float refx, refy;
    {
        int lvlH, lvlW, idx;
        if (s < 6400)      { lvlH = 80; lvlW = 80; idx = s; }
        else if (s < 8000) { lvlH = 40; lvlW = 40; idx = s - 6400; }
        else if (s < 8400) { lvlH = 20; lvlW = 20; idx = s - 8000; }
        else               { lvlH = 10; lvlW = 10; idx = s - 8400; }
        refx = ((idx % lvlW) + 0.5f) / (float)lvlW;
        refy = ((idx / lvlW) + 0.5f) / (float)lvlH;
    }

    const float* base = ol + (size_t)bs * NPK;

    float w[16];
    {
        const float4* lg4 = (const float4*)(base + 256 + head * 16);
        float4 a0 = __ldg(lg4 + 0), a1 = __ldg(lg4 + 1);
        float4 a2 = __ldg(lg4 + 2), a3 = __ldg(lg4 + 3);
        w[0]=a0.x; w[1]=a0.y; w[2]=a0.z; w[3]=a0.w;
        w[4]=a1.x; w[5]=a1.y; w[6]=a1.z; w[7]=a1.w;
        w[8]=a2.x; w[9]=a2.y; w[10]=a2.z; w[11]=a2.w;
        w[12]=a3.x; w[13]=a3.y; w[14]=a3.z; w[15]=a3.w;
        float mx = w[0];
        #pragma unroll
        for (int i = 1; i < 16; i++) mx = fmaxf(mx, w[i]);
        float sum = 0.f;
        #pragma unroll
        for (int i = 0; i < 16; i++) { w[i] = __expf(w[i] - mx); sum += w[i]; }
        const float inv = 1.0f / sum;
        #pragma unroll
        for (int i = 0; i < 16; i++) w[i] *= inv;
    }

    float4 o4[8];
    {
        const float4* op = (const float4*)(base + head * 32);
        #pragma unroll
        for (int i = 0; i < 8; i++) o4[i] = __ldg(op + i);
    }

    const int d0 = head * DD + li * 4;
    float4 acc = make_float4(0.f, 0.f, 0.f, 0.f);

    const int LW[4] = {80, 40, 20, 10};
    const int LH[4] = {80, 40, 20, 10};
    const int LS[4] = {0, 6400, 8000, 8400};

    #pragma unroll
    for (int l = 0; l < 4; l++) {
        const int Wl = LW[l], Hl = LH[l];
        const float rxm = refx * (float)Wl - 0.5f;
        const float rym = refy * (float)Hl - 0.5f;
        const char* vb = (const char*)(value + (size_t)(rowb + LS[l]) * CC + d0);
        const int ROWB = Wl * (CC * 2);
        #pragma unroll
        for (int p = 0; p < 4; p++) {
            const int pi = l * 4 + p;
            const float ox = (pi & 1) ? o4[pi >> 1].z : o4[pi >> 1].x;
            const float oy = (pi & 1) ? o4[pi >> 1].w : o4[pi >> 1].y;
            const float aw = w[pi];

            const float x = rxm + ox;
            const float y = rym + oy;
            const int x0 = __float2int_rd(x);
            const int y0 = __float2int_rd(y);
            const float fx = x - (float)x0;
            const float fy = y - (float)y0;

            const bool px0 = (unsigned)x0 < (unsigned)Wl;
            const bool px1 = (unsigned)(x0 + 1) < (unsigned)Wl;
            const bool py0 = (unsigned)y0 < (unsigned)Hl;
            const bool py1 = (unsigned)(y0 + 1) < (unsigned)Hl;

            const char* pc = vb + ((size_t)(y0 * Wl + x0) * (CC * 2));
            uint2 u00 = make_uint2(0u, 0u);
            uint2 u01 = u00, u10 = u00, u11 = u00;
            if (px0 & py0) u00 = *(const uint2*)(pc);
            if (px1 & py0) u01 = *(const uint2*)(pc + CC * 2);
            if (px0 & py1) u10 = *(const uint2*)(pc + ROWB);
            if (px1 & py1) u11 = *(const uint2*)(pc + ROWB + CC * 2);

            const float gx0 = 1.f - fx;
            const float wy0 = (1.f - fy) * aw;
            const float wy1 = fy * aw;
            const __half2 hw00 = __float2half2_rn(gx0 * wy0);
            const __half2 hw01 = __float2half2_rn(fx * wy0);
            const __half2 hw10 = __float2half2_rn(gx0 * wy1);
            const __half2 hw11 = __float2half2_rn(fx * wy1);

            // per-point bilinear sum in half2, accumulate in fp32
            __half2 p0 = __hmul2(hw00, *(const __half2*)&u00.x);
            __half2 p1 = __hmul2(hw00, *(const __half2*)&u00.y);
            p0 = __hfma2(hw01, *(const __half2*)&u01.x, p0);
            p1 = __hfma2(hw01, *(const __half2*)&u01.y, p1);
            p0 = __hfma2(hw10, *(const __half2*)&u10.x, p0);
            p1 = __hfma2(hw10, *(const __half2*)&u10.y, p1);
            p0 = __hfma2(hw11, *(const __half2*)&u11.x, p0);
            p1 = __hfma2(hw11, *(const __half2*)&u11.y, p1);

            float2 f0 = __half22float2(p0);
            float2 f1 = __half22float2(p1);
            acc.x += f0.x; acc.y += f0.y;
            acc.z += f1.x; acc.w += f1.y;
        }
    }
    __half2* o = (__half2*)(out + (size_t)bs * CC + d0);
    o[0] = __floats2half2_rn(acc.x, acc.y);
    o[1] = __floats2half2_rn(acc.z, acc.w);
}

// ---------------- fused residual + LayerNorm -----------------------------------
template<bool HCOPY>
__global__ void ln_residual(const float* __restrict__ a, const float* __restrict__ r,
                            const float* __restrict__ g, const float* __restrict__ bta,
                            float* __restrict__ out, __half* __restrict__ outh) {
    const int row = blockIdx.x;
    const int t = threadIdx.x;
    const float4 va = ((const float4*)(a + (size_t)row * CC))[t];
    const float4 vr = ((const float4*)(r + (size_t)row * CC))[t];
    float x0 = va.x + vr.x, x1 = va.y + vr.y, x2 = va.z + vr.z, x3 = va.w + vr.w;

    float sum = x0 + x1 + x2 + x3;
    float sq  = x0 * x0 + x1 * x1 + x2 * x2 + x3 * x3;
    #pragma unroll
    for (int o = 16; o; o >>= 1) {
        sum += __shfl_xor_sync(0xffffffffu, sum, o);
        sq  += __shfl_xor_sync(0xffffffffu, sq,  o);
    }
    __shared__ float sh[8];
    const int wid = t >> 5, lane = t & 31;
    if (lane == 0) { sh[wid] = sum; sh[wid + 4] = sq; }
    __syncthreads();
    sum = sh[0] + sh[1] + sh[2] + sh[3];
    sq  = sh[4] + sh[5] + sh[6] + sh[7];

    const float mean = sum * (1.0f / CC);
    const float var  = sq * (1.0f / CC) - mean * mean;
    const float istd = rsqrtf(var + 1e-5f);

    const float4 vg = ((const float4*)g)[t];
    const float4 vb = ((const float4*)bta)[t];
    float4 o4;
    o4.x = (x0 - mean) * istd * vg.x + vb.x;
    o4.y = (x1 - mean) * istd * vg.y + vb.y;
    o4.z = (x2 - mean) * istd * vg.z + vb.z;
    o4.w = (x3 - mean) * istd * vg.w + vb.w;
    ((float4*)(out + (size_t)row * CC))[t] = o4;
    if (HCOPY) {
        __half2* oh = (__half2*)(outh + (size_t)row * CC) + t * 2;
        oh[0] = __floats2half2_rn(o4.x, o4.y);
        oh[1] = __floats2half2_rn(o4.z, o4.w);
    }
}

// ---------------- launch ------------------------------------------------------
static void* symv(const void* s) {
    void* p = nullptr;
    cudaGetSymbolAddress(&p, s);
    return p;
}

extern "C" void kernel_launch(void* const* d_in, const int* in_sizes, int n_in,
                              void* d_out, int out_size) {
    const float* src    = (const float*)d_in[0];
    const float* pos    = (const float*)d_in[1];
    const float* w_off  = (const float*)d_in[2];
    const float* b_off  = (const float*)d_in[3];
    const float* w_attn = (const float*)d_in[4];
    const float* b_attn = (const float*)d_in[5];
    const float* w_val  = (const float*)d_in[6];
    const float* b_val  = (const float*)d_in[7];
    const float* w_out  = (const float*)d_in[8];
    const float* b_out  = (const float*)d_in[9];
    const float* ln1_g  = (const float*)d_in[10];
    const float* ln1_b  = (const float*)d_in[11];
    const float* w1     = (const float*)d_in[12];
    const float* b1     = (const float*)d_in[13];
    const float* w2     = (const float*)d_in[14];
    const float* b2     = (const float*)d_in[15];
    const float* ln2_g  = (const float*)d_in[16];
    const float* ln2_b  = (const float*)d_in[17];
    float* out = (float*)d_out;

    __half* srch = (__half*)symv(g_srch);
    __half* qh   = (__half*)symv(g_qh);
    __half* valh = (__half*)symv(g_valh);
    float*  olb  = (float*)symv(g_ol);
    __half* smp  = (__half*)symv(g_smp);
    float*  tmp  = (float*)symv(g_tmp);
    float*  x    = (float*)symv(g_x);
    __half* xh   = (__half*)symv(g_xh);
    __half* hid  = (__half*)symv(g_hid);
    __half* wvh  = (__half*)symv(g_wvh);
    __half* wph  = (__half*)symv(g_wph);
    float*  bp   = (float*)symv(g_bp);
    __half* woh  = (__half*)symv(g_woh);
    __half* w1h  = (__half*)symv(g_w1h);
    __half* w2h  = (__half*)symv(g_w2h);

    // REQUIRED: dynamic smem 71.7KB > 48KB default
    cudaFuncSetAttribute(hgemm<false,false>, cudaFuncAttributeMaxDynamicSharedMemorySize, SMEM_BYTES);
    cudaFuncSetAttribute(hgemm<true,true>,   cudaFuncAttributeMaxDynamicSharedMemorySize, SMEM_BYTES);
    cudaFuncSetAttribute(hgemm_dual,         cudaFuncAttributeMaxDynamicSharedMemorySize, SMEM_BYTES);

    const int mblocks = (MT + 127) / 128;

    // 0. prep
    {
        int total = N4ADD + SEG_W2 + CC * NPK;
        prep_all<<<(total + 255) / 256, 256>>>(src, pos, qh, srch,
                                               w_val, w_out, w1, w2,
                                               w_off, w_attn, b_off, b_attn,
                                               wvh, woh, w1h, w2h, wph, bp);
    }
    // 1. fused: value GEMM (fp16 out) + off|lgt GEMM
    hgemm_dual<<<dim3(CC / 128, mblocks, 2), 256, SMEM_BYTES>>>(
        srch, wvh, b_val, valh, qh, wph, bp, olb);
    // 2. deformable sampling
    {
        int warps = MT * 4;
        int blocks = (warps * 32 + 255) / 256;
        sample_kernel<<<blocks, 256>>>(valh, olb, smp);
    }
    // 3. attn_out = smp @ woh + b_out (fp32)
    hgemm<false,false><<<dim3(CC / 128, mblocks), 256, SMEM_BYTES>>>(smp, woh, b_out, tmp, MT, CC, CC);
    // 4. x = LN(src + attn_out), + fp16 copy
    ln_residual<true><<<MT, 128>>>(src, tmp, ln1_g, ln1_b, x, xh);
    // 5. hid = relu(xh @ w1h + b1) (fp16 out)
    hgemm<true,true><<<dim3(DFFN / 128, mblocks), 256, SMEM_BYTES>>>(xh, w1h, b1, hid, MT, DFFN, CC);
    // 6. ffn = hid @ w2h + b2 (fp32)
    hgemm<false,false><<<dim3(CC / 128, mblocks), 256, SMEM_BYTES>>>(hid, w2h, b2, tmp, MT, CC, DFFN);
    // 7. out = LN(x + ffn)
    ln_residual<false><<<MT, 128>>>(x, tmp, ln2_g, ln2_b, out, nullptr);
}

// round 17
// speedup vs baseline: 1.4778x; 1.4778x over previous
#include <cuda_runtime.h>
#include <cuda_fp16.h>
#include <math.h>
#include <stdint.h>

#define BB 2
#define SS 8500
#define CC 512
#define HH 8
#define DD 64
#define DFFN 1024
#define MT (BB*SS)   // 17000
#define NPK 384      // packed off(256)+attn(128)

// GEMM tiling: CTA 128x128, 8 warps x (64x32), BK=32, 3 stages, fp16 inputs (R15 proven)
#define BK 32
#define PAh 40
#define PBh 136
#define ASTG (128*PAh)
#define BSTG (BK*PBh)
#define STG  (ASTG+BSTG)
#define NSTAGE 3
#define SMEM_BYTES (NSTAGE*STG*2)   // 56832 B

// ---------------- scratch ------------------------------------------------------
__device__ __half g_srch[MT*CC];
__device__ __half g_qh  [MT*CC];
__device__ __half g_valh[MT*CC];
__device__ float  g_ol  [MT*NPK];
__device__ __half g_smp [MT*CC];
__device__ float  g_tmp [MT*CC];
__device__ float  g_x   [MT*CC];
__device__ __half g_xh  [MT*CC];
__device__ __half g_hid [MT*DFFN];
__device__ __half g_wvh [CC*CC];
__device__ __half g_wph [CC*NPK];
__device__ float  g_bp  [NPK];
__device__ __half g_woh [CC*CC];
__device__ __half g_w1h [CC*DFFN];
__device__ __half g_w2h [DFFN*CC];

__device__ __forceinline__ uint32_t smem_u32(const void* p) {
    return (uint32_t)__cvta_generic_to_shared(p);
}

__device__ __forceinline__ void ldm_x4(uint32_t* r, uint32_t addr) {
    asm volatile("ldmatrix.sync.aligned.m8n8.x4.shared.b16 {%0,%1,%2,%3}, [%4];"
                 : "=r"(r[0]), "=r"(r[1]), "=r"(r[2]), "=r"(r[3]) : "r"(addr));
}
__device__ __forceinline__ void ldm_x4t(uint32_t* r, uint32_t addr) {
    asm volatile("ldmatrix.sync.aligned.m8n8.x4.trans.shared.b16 {%0,%1,%2,%3}, [%4];"
                 : "=r"(r[0]), "=r"(r[1]), "=r"(r[2]), "=r"(r[3]) : "r"(addr));
}
__device__ __forceinline__ void mma_f16(float* d, const uint32_t* a, uint32_t b0, uint32_t b1) {
    asm volatile(
        "mma.sync.aligned.m16n8k16.row.col.f32.f16.f16.f32 "
        "{%0,%1,%2,%3}, {%4,%5,%6,%7}, {%8,%9}, {%0,%1,%2,%3};"
        : "+f"(d[0]), "+f"(d[1]), "+f"(d[2]), "+f"(d[3])
        : "r"(a[0]), "r"(a[1]), "r"(a[2]), "r"(a[3]), "r"(b0), "r"(b1));
}

// ---------------- one-shot prep -------------------------------------------------
#define N4ADD (MT*CC/4)
#define SEG_WV 65536
#define SEG_WO 131072
#define SEG_W1 262144
#define SEG_W2 393216
__global__ void prep_all(const float* __restrict__ src, const float* __restrict__ pos,
                         __half* __restrict__ qh, __half* __restrict__ srch,
                         const float* __restrict__ wv, const float* __restrict__ wo,
                         const float* __restrict__ w1, const float* __restrict__ w2,
                         const float* __restrict__ w_off, const float* __restrict__ w_attn,
                         const float* __restrict__ b_off, const float* __restrict__ b_attn,
                         __half* __restrict__ wvh, __half* __restrict__ woh,
                         __half* __restrict__ w1h, __half* __restrict__ w2h,
                         __half* __restrict__ wph, float* __restrict__ bp) {
    int i = blockIdx.x * blockDim.x + threadIdx.x;
    if (i < N4ADD) {
        float4 x = ((const float4*)src)[i];
        float4 y = ((const float4*)pos)[i];
        __half2* qo = (__half2*)qh + i * 2;
        __half2* so = (__half2*)srch + i * 2;
        qo[0] = __floats2half2_rn(x.x + y.x, x.y + y.y);
        qo[1] = __floats2half2_rn(x.z + y.z, x.w + y.w);
        so[0] = __floats2half2_rn(x.x, x.y);
        so[1] = __floats2half2_rn(x.z, x.w);
        return;
    }
    int c4 = i - N4ADD;
    if (c4 < SEG_W2) {
        const float* in;
        __half* out;
        int j;
        if (c4 < SEG_WV)      { in = wv; out = wvh; j = c4; }
        else if (c4 < SEG_WO) { in = wo; out = woh; j = c4 - SEG_WV; }
        else if (c4 < SEG_W1) { in = w1; out = w1h; j = c4 - SEG_WO; }
        else                  { in = w2; out = w2h; j = c4 - SEG_W1; }
        float4 v = ((const float4*)in)[j];
        __half2* o = (__half2*)out + j * 2;
        o[0] = __floats2half2_rn(v.x, v.y);
        o[1] = __floats2half2_rn(v.z, v.w);
        return;
    }
    int j = c4 - SEG_W2;
    if (j < CC * NPK) {
        int r = j / NPK, c = j % NPK;
        float v = (c < 256) ? w_off[r * 256 + c] : w_attn[r * 128 + (c - 256)];
        wph[j] = __float2half_rn(v);
    }
    if (j < NPK) bp[j] = (j < 256) ? b_off[j] : b_attn[j - 256];
}

// ================= fp16 GEMM body (BK=32, 3-stage, single-sync) ===============
template<bool RELU, bool HOUT>
__device__ __forceinline__ void hgemm_body(const __half* __restrict__ A,
                                           const __half* __restrict__ Bm,
                                           const float* __restrict__ bias,
                                           void* __restrict__ Cv,
                                           int M, int N, int K, __half* smh)
{
    const int tid  = threadIdx.x;
    const int lane = tid & 31;
    const int wid  = tid >> 5;
    const int wm   = (wid & 1) * 64;
    const int wn   = (wid >> 1) * 32;
    const int mb   = blockIdx.y * 128;
    const int nb   = blockIdx.x * 128;
    const int g    = lane >> 2;
    const int t    = lane & 3;
    const int l15  = lane & 15;
    const int lhi  = lane >> 4;

    float acc[4][4][4];
    #pragma unroll
    for (int i = 0; i < 4; i++)
        #pragma unroll
        for (int j = 0; j < 4; j++)
            #pragma unroll
            for (int r = 0; r < 4; r++) acc[i][j][r] = 0.f;

#define LOADH(buf, kt)                                                             \
    {                                                                              \
        __half* as = smh + (buf) * STG;                                            \
        __half* bs = smh + (buf) * STG + ASTG;                                     \
        _Pragma("unroll")                                                          \
        for (int i = 0; i < 2; i++) {                                              \
            int lin = tid + 256 * i;                                               \
            int row = lin >> 2;                                                    \
            int chk = (lin & 3) * 8;                                               \
            const __half* gp = A + (size_t)(mb + row) * K + (kt) + chk;            \
            uint32_t sa = smem_u32(as + row * PAh + chk);                          \
            int zf = (mb + row < M) ? 16 : 0;                                      \
            asm volatile("cp.async.cg.shared.global [%0], [%1], 16, %2;"           \
                         :: "r"(sa), "l"(gp), "r"(zf));                            \
        }                                                                          \
        _Pragma("unroll")                                                          \
        for (int i = 0; i < 2; i++) {                                              \
            int lin = tid + 256 * i;                                               \
            int k = lin >> 4;                                                      \
            int chk = (lin & 15) * 8;                                              \
            const __half* gp = Bm + (size_t)((kt) + k) * N + nb + chk;             \
            uint32_t sa = smem_u32(bs + k * PBh + chk);                            \
            asm volatile("cp.async.cg.shared.global [%0], [%1], 16;"               \
                         :: "r"(sa), "l"(gp));                                     \
        }                                                                          \
        asm volatile("cp.async.commit_group;");                                    \
    }

    const int NIT = K / BK;
    LOADH(0, 0);
    LOADH(1, BK);

    for (int it = 0; it < NIT; it++) {
        asm volatile("cp.async.wait_group 1;");
        __syncthreads();
        if (it + 2 < NIT) {
            LOADH((it + 2) % 3, (it + 2) * BK);
        } else {
            asm volatile("cp.async.commit_group;");
        }

        const int buf = it % 3;
        const __half* ab = smh + buf * STG;
        const __half* bb = smh + buf * STG + ASTG;
        #pragma unroll
        for (int k0 = 0; k0 < BK; k0 += 16) {
            uint32_t af[4][4];
            uint32_t bf[2][4];
            #pragma unroll
            for (int mt = 0; mt < 4; mt++) {
                uint32_t sa = smem_u32((__half*)ab + (wm + mt * 16 + l15) * PAh + k0 + lhi * 8);
                ldm_x4(af[mt], sa);
            }
            #pragma unroll
            for (int nh = 0; nh < 2; nh++) {
                uint32_t sa = smem_u32((__half*)bb + (k0 + l15) * PBh + wn + nh * 16 + lhi * 8);
                ldm_x4t(bf[nh], sa);
            }
            #pragma unroll
            for (int mt = 0; mt < 4; mt++)
                #pragma unroll
                for (int nt = 0; nt < 4; nt++)
                    mma_f16(acc[mt][nt], af[mt], bf[nt >> 1][(nt & 1) * 2], bf[nt >> 1][(nt & 1) * 2 + 1]);
        }
    }
#undef LOADH

    #pragma unroll
    for (int mt = 0; mt < 4; mt++) {
        const int r0 = mb + wm + mt * 16 + g;
        const int r1 = r0 + 8;
        #pragma unroll
        for (int nt = 0; nt < 4; nt++) {
            const int c = nb + wn + nt * 8 + t * 2;
            const float b0 = __ldg(bias + c);
            const float b1 = __ldg(bias + c + 1);
            float v0 = acc[mt][nt][0] + b0;
            float v1 = acc[mt][nt][1] + b1;
            float v2 = acc[mt][nt][2] + b0;
            float v3 = acc[mt][nt][3] + b1;
            if (RELU) {
                v0 = fmaxf(v0, 0.f); v1 = fmaxf(v1, 0.f);
                v2 = fmaxf(v2, 0.f); v3 = fmaxf(v3, 0.f);
            }
            if (HOUT) {
                __half* Ch = (__half*)Cv;
                if (r0 < M) *(__half2*)(Ch + (size_t)r0 * N + c) = __floats2half2_rn(v0, v1);
                if (r1 < M) *(__half2*)(Ch + (size_t)r1 * N + c) = __floats2half2_rn(v2, v3);
            } else {
                float* Cf = (float*)Cv;
                if (r0 < M) *(float2*)(Cf + (size_t)r0 * N + c) = make_float2(v0, v1);
                if (r1 < M) *(float2*)(Cf + (size_t)r1 * N + c) = make_float2(v2, v3);
            }
        }
    }
}

template<bool RELU, bool HOUT>
__global__ __launch_bounds__(256, 2)
void hgemm(const __half* __restrict__ A, const __half* __restrict__ Bm,
           const float* __restrict__ bias, void* __restrict__ Cv,
           int M, int N, int K)
{
    extern __shared__ __align__(16) __half smh[];
    hgemm_body<RELU, HOUT>(A, Bm, bias, Cv, M, N, K, smh);
}

// fused: z=0 value GEMM (N=512, fp16 out), z=1 off|lgt GEMM (N=384, fp32 out)
__global__ __launch_bounds__(256, 2)
void hgemm_dual(const __half* __restrict__ A0, const __half* __restrict__ B0,
                const float* __restrict__ bias0, __half* __restrict__ C0,
                const __half* __restrict__ A1, const __half* __restrict__ B1,
                const float* __restrict__ bias1, float* __restrict__ C1)
{
    extern __shared__ __align__(16) __half smh[];
    if (blockIdx.z == 0) {
        hgemm_body<false, true>(A0, B0, bias0, C0, MT, CC, CC, smh);
    } else {
        if (blockIdx.x >= NPK / 128) return;
        hgemm_body<false, false>(A1, B1, bias1, C1, MT, NPK, CC, smh);
    }
}

// ---------------- deformable sampling: hfma2 bilinear -------------------------
__global__ void sample_kernel(const __half* __restrict__ value,
                              const float* __restrict__ ol,
                              __half* __restrict__ out) {
    int gw = (blockIdx.x * blockDim.x + threadIdx.x) >> 5;
    if (gw >= MT * 4) return;
    const int lane = threadIdx.x & 31;
    const int hp = gw & 3;
    const int bs = gw >> 2;
    const int s  = bs % SS;
    const int rowb = bs - s;
    const int hl = lane >> 4;
    const int li = lane & 15;
    const int head = hp * 2 + hl;

    float refx, refy;
    {
        int lvlH, lvlW, idx;
        if (s < 6400)      { lvlH = 80; lvlW = 80; idx = s; }
        else if (s < 8000) { lvlH = 40; lvlW = 40; idx = s - 6400; }
        else if (s < 8400) { lvlH = 20; lvlW = 20; idx = s - 8000; }
        else               { lvlH = 10; lvlW = 10; idx = s - 8400; }
        refx = ((idx % lvlW) + 0.5f) / (float)lvlW;
        refy = ((idx / lvlW) + 0.5f) / (float)lvlH;
    }

    const float* base = ol + (size_t)bs * NPK;

    float w[16];
    {
        const float4* lg4 = (const float4*)(base + 256 + head * 16);
        float4 a0 = __ldg(lg4 + 0), a1 = __ldg(lg4 + 1);
        float4 a2 = __ldg(lg4 + 2), a3 = __ldg(lg4 + 3);
        w[0]=a0.x; w[1]=a0.y; w[2]=a0.z; w[3]=a0.w;
        w[4]=a1.x; w[5]=a1.y; w[6]=a1.z; w[7]=a1.w;
        w[8]=a2.x; w[9]=a2.y; w[10]=a2.z; w[11]=a2.w;
        w[12]=a3.x; w[13]=a3.y; w[14]=a3.z; w[15]=a3.w;
        float mx = w[0];
        #pragma unroll
        for (int i = 1; i < 16; i++) mx = fmaxf(mx, w[i]);
        float sum = 0.f;
        #pragma unroll
        for (int i = 0; i < 16; i++) { w[i] = __expf(w[i] - mx); sum += w[i]; }
        const float inv = 1.0f / sum;
        #pragma unroll
        for (int i = 0; i < 16; i++) w[i] *= inv;
    }

    float4 o4[8];
    {
        const float4* op = (const float4*)(base + head * 32);
        #pragma unroll
        for (int i = 0; i < 8; i++) o4[i] = __ldg(op + i);
    }

    const int d0 = head * DD + li * 4;
    float4 acc = make_float4(0.f, 0.f, 0.f, 0.f);

    const int LW[4] = {80, 40, 20, 10};
    const int LH[4] = {80, 40, 20, 10};
    const int LS[4] = {0, 6400, 8000, 8400};

    #pragma unroll
    for (int l = 0; l < 4; l++) {
        const int Wl = LW[l], Hl = LH[l];
        const float rxm = refx * (float)Wl - 0.5f;
        const float rym = refy * (float)Hl - 0.5f;
        const char* vb = (const char*)(value + (size_t)(rowb + LS[l]) * CC + d0);
        const int ROWB = Wl * (CC * 2);
        #pragma unroll
        for (int p = 0; p < 4; p++) {
            const int pi = l * 4 + p;
            const float ox = (pi & 1) ? o4[pi >> 1].z : o4[pi >> 1].x;
            const float oy = (pi & 1) ? o4[pi >> 1].w : o4[pi >> 1].y;
            const float aw = w[pi];

            const float x = rxm + ox;
            const float y = rym + oy;
            const int x0 = __float2int_rd(x);
            const int y0 = __float2int_rd(y);
            const float fx = x - (float)x0;
            const float fy = y - (float)y0;

            const bool px0 = (unsigned)x0 < (unsigned)Wl;
            const bool px1 = (unsigned)(x0 + 1) < (unsigned)Wl;
            const bool py0 = (unsigned)y0 < (unsigned)Hl;
            const bool py1 = (unsigned)(y0 + 1) < (unsigned)Hl;

            const char* pc = vb + ((size_t)(y0 * Wl + x0) * (CC * 2));
            uint2 u00 = make_uint2(0u, 0u);
            uint2 u01 = u00, u10 = u00, u11 = u00;
            if (px0 & py0) u00 = *(const uint2*)(pc);
            if (px1 & py0) u01 = *(const uint2*)(pc + CC * 2);
            if (px0 & py1) u10 = *(const uint2*)(pc + ROWB);
            if (px1 & py1) u11 = *(const uint2*)(pc + ROWB + CC * 2);

            const float gx0 = 1.f - fx;
            const float wy0 = (1.f - fy) * aw;
            const float wy1 = fy * aw;
            const __half2 hw00 = __float2half2_rn(gx0 * wy0);
            const __half2 hw01 = __float2half2_rn(fx * wy0);
            const __half2 hw10 = __float2half2_rn(gx0 * wy1);
            const __half2 hw11 = __float2half2_rn(fx * wy1);

            __half2 p0 = __hmul2(hw00, *(const __half2*)&u00.x);
            __half2 p1 = __hmul2(hw00, *(const __half2*)&u00.y);
            p0 = __hfma2(hw01, *(const __half2*)&u01.x, p0);
            p1 = __hfma2(hw01, *(const __half2*)&u01.y, p1);
            p0 = __hfma2(hw10, *(const __half2*)&u10.x, p0);
            p1 = __hfma2(hw10, *(const __half2*)&u10.y, p1);
            p0 = __hfma2(hw11, *(const __half2*)&u11.x, p0);
            p1 = __hfma2(hw11, *(const __half2*)&u11.y, p1);

            float2 f0 = __half22float2(p0);
            float2 f1 = __half22float2(p1);
            acc.x += f0.x; acc.y += f0.y;
            acc.z += f1.x; acc.w += f1.y;
        }
    }
    __half2* o = (__half2*)(out + (size_t)bs * CC + d0);
    o[0] = __floats2half2_rn(acc.x, acc.y);
    o[1] = __floats2half2_rn(acc.z, acc.w);
}

// ---------------- fused residual + LayerNorm -----------------------------------
template<bool HCOPY>
__global__ void ln_residual(const float* __restrict__ a, const float* __restrict__ r,
                            const float* __restrict__ g, const float* __restrict__ bta,
                            float* __restrict__ out, __half* __restrict__ outh) {
    const int row = blockIdx.x;
    const int t = threadIdx.x;
    const float4 va = ((const float4*)(a + (size_t)row * CC))[t];
    const float4 vr = ((const float4*)(r + (size_t)row * CC))[t];
    float x0 = va.x + vr.x, x1 = va.y + vr.y, x2 = va.z + vr.z, x3 = va.w + vr.w;

    float sum = x0 + x1 + x2 + x3;
    float sq  = x0 * x0 + x1 * x1 + x2 * x2 + x3 * x3;
    #pragma unroll
    for (int o = 16; o; o >>= 1) {
        sum += __shfl_xor_sync(0xffffffffu, sum, o);
        sq  += __shfl_xor_sync(0xffffffffu, sq,  o);
    }
    __shared__ float sh[8];
    const int wid = t >> 5, lane = t & 31;
    if (lane == 0) { sh[wid] = sum; sh[wid + 4] = sq; }
    __syncthreads();
    sum = sh[0] + sh[1] + sh[2] + sh[3];
    sq  = sh[4] + sh[5] + sh[6] + sh[7];

    const float mean = sum * (1.0f / CC);
    const float var  = sq * (1.0f / CC) - mean * mean;
    const float istd = rsqrtf(var + 1e-5f);

    const float4 vg = ((const float4*)g)[t];
    const float4 vb = ((const float4*)bta)[t];
    float4 o4;
    o4.x = (x0 - mean) * istd * vg.x + vb.x;
    o4.y = (x1 - mean) * istd * vg.y + vb.y;
    o4.z = (x2 - mean) * istd * vg.z + vb.z;
    o4.w = (x3 - mean) * istd * vg.w + vb.w;
    ((float4*)(out + (size_t)row * CC))[t] = o4;
    if (HCOPY) {
        __half2* oh = (__half2*)(outh + (size_t)row * CC) + t * 2;
        oh[0] = __floats2half2_rn(o4.x, o4.y);
        oh[1] = __floats2half2_rn(o4.z, o4.w);
    }
}

// ---------------- launch ------------------------------------------------------
static void* symv(const void* s) {
    void* p = nullptr;
    cudaGetSymbolAddress(&p, s);
    return p;
}

extern "C" void kernel_launch(void* const* d_in, const int* in_sizes, int n_in,
                              void* d_out, int out_size) {
    const float* src    = (const float*)d_in[0];
    const float* pos    = (const float*)d_in[1];
    const float* w_off  = (const float*)d_in[2];
    const float* b_off  = (const float*)d_in[3];
    const float* w_attn = (const float*)d_in[4];
    const float* b_attn = (const float*)d_in[5];
    const float* w_val  = (const float*)d_in[6];
    const float* b_val  = (const float*)d_in[7];
    const float* w_out  = (const float*)d_in[8];
    const float* b_out  = (const float*)d_in[9];
    const float* ln1_g  = (const float*)d_in[10];
    const float* ln1_b  = (const float*)d_in[11];
    const float* w1     = (const float*)d_in[12];
    const float* b1     = (const float*)d_in[13];
    const float* w2     = (const float*)d_in[14];
    const float* b2     = (const float*)d_in[15];
    const float* ln2_g  = (const float*)d_in[16];
    const float* ln2_b  = (const float*)d_in[17];
    float* out = (float*)d_out;

    __half* srch = (__half*)symv(g_srch);
    __half* qh   = (__half*)symv(g_qh);
    __half* valh = (__half*)symv(g_valh);
    float*  olb  = (float*)symv(g_ol);
    __half* smp  = (__half*)symv(g_smp);
    float*  tmp  = (float*)symv(g_tmp);
    float*  x    = (float*)symv(g_x);
    __half* xh   = (__half*)symv(g_xh);
    __half* hid  = (__half*)symv(g_hid);
    __half* wvh  = (__half*)symv(g_wvh);
    __half* wph  = (__half*)symv(g_wph);
    float*  bp   = (float*)symv(g_bp);
    __half* woh  = (__half*)symv(g_woh);
    __half* w1h  = (__half*)symv(g_w1h);
    __half* w2h  = (__half*)symv(g_w2h);

    // REQUIRED: dynamic smem 56.8KB > 48KB default
    cudaFuncSetAttribute(hgemm<false,false>, cudaFuncAttributeMaxDynamicSharedMemorySize, SMEM_BYTES);
    cudaFuncSetAttribute(hgemm<true,true>,   cudaFuncAttributeMaxDynamicSharedMemorySize, SMEM_BYTES);
    cudaFuncSetAttribute(hgemm_dual,         cudaFuncAttributeMaxDynamicSharedMemorySize, SMEM_BYTES);

    const int mblocks = (MT + 127) / 128;

    // 0. prep
    {
        int total = N4ADD + SEG_W2 + CC * NPK;
        prep_all<<<(total + 255) / 256, 256>>>(src, pos, qh, srch,
                                               w_val, w_out, w1, w2,
                                               w_off, w_attn, b_off, b_attn,
                                               wvh, woh, w1h, w2h, wph, bp);
    }
    // 1. fused: value GEMM (fp16 out) + off|lgt GEMM
    hgemm_dual<<<dim3(CC / 128, mblocks, 2), 256, SMEM_BYTES>>>(
        srch, wvh, b_val, valh, qh, wph, bp, olb);
    // 2. deformable sampling
    {
        int warps = MT * 4;
        int blocks = (warps * 32 + 255) / 256;
        sample_kernel<<<blocks, 256>>>(valh, olb, smp);
    }
    // 3. attn_out = smp @ woh + b_out (fp32)
    hgemm<false,false><<<dim3(CC / 128, mblocks), 256, SMEM_BYTES>>>(smp, woh, b_out, tmp, MT, CC, CC);
    // 4. x = LN(src + attn_out), + fp16 copy
    ln_residual<true><<<MT, 128>>>(src, tmp, ln1_g, ln1_b, x, xh);
    // 5. hid = relu(xh @ w1h + b1) (fp16 out)
    hgemm<true,true><<<dim3(DFFN / 128, mblocks), 256, SMEM_BYTES>>>(xh, w1h, b1, hid, MT, DFFN, CC);
    // 6. ffn = hid @ w2h + b2 (fp32)
    hgemm<false,false><<<dim3(CC / 128, mblocks), 256, SMEM_BYTES>>>(hid, w2h, b2, tmp, MT, CC, DFFN);
    // 7. out = LN(x + ffn)
    ln_residual<false><<<MT, 128>>>(x, tmp, ln2_g, ln2_b, out, nullptr);
}